// round 15
// baseline (speedup 1.0000x reference)
#include <cuda_runtime.h>
#include <cuda_bf16.h>
#include <cuda_fp16.h>
#include <math.h>

// Problem constants
#define NB 4
#define NT 4096
#define NC 1024
#define ND 64
#define BQ 64           // q rows per CTA (attention)
#define BK 64           // kv tokens per tile (attention)
#define NSPLIT 2        // kv-range splits (flash-decode)

// Pre-split projections. Q/K: packed bf16x2 hi/lo (32 uints per token row),
// Q pre-scaled by 8*log2(e). V: packed fp16x2 single (32 uints per row).
__device__ unsigned g_qhi[NB * NT * 32];
__device__ unsigned g_qlo[NB * NT * 32];
__device__ unsigned g_khi[NB * NT * 32];
__device__ unsigned g_klo[NB * NT * 32];
__device__ unsigned g_vh [NB * NT * 32];
// Pre-split W (packed bf16x2 hi/lo): rows 0-63 Wq, 64-127 Wk, 128-191 Wv
__device__ unsigned g_whi[192 * 512];
__device__ unsigned g_wlo[192 * 512];
// KV-split partials: unnormalized O + per-row (m, l), exp2 domain
__device__ float g_po[NSPLIT * NB * NT * ND];
__device__ float g_pm[NSPLIT * NB * NT];
__device__ float g_pl[NSPLIT * NB * NT];

// ===========================================================================
// Helpers
// ===========================================================================
__device__ __forceinline__ unsigned smem_to_u32(const void* p) {
    unsigned a;
    asm("{ .reg .u64 t; cvta.to.shared.u64 t, %1; cvt.u32.u64 %0, t; }"
        : "=r"(a) : "l"(p));
    return a;
}

__device__ __forceinline__ float ex2(float x) {
    float y;
    asm("ex2.approx.ftz.f32 %0, %1;" : "=f"(y) : "f"(x));
    return y;
}

// bf16 hi/lo split of a float pair, packed little-endian (x in low half)
__device__ __forceinline__ void split2(float x, float y, unsigned& hp, unsigned& lp) {
    __nv_bfloat16 hx = __float2bfloat16(x);
    __nv_bfloat16 hy = __float2bfloat16(y);
    float rx = x - __bfloat162float(hx);
    float ry = y - __bfloat162float(hy);
    __nv_bfloat16 lx = __float2bfloat16(rx);
    __nv_bfloat16 ly = __float2bfloat16(ry);
    hp = ((unsigned)__bfloat16_as_ushort(hy) << 16) | __bfloat16_as_ushort(hx);
    lp = ((unsigned)__bfloat16_as_ushort(ly) << 16) | __bfloat16_as_ushort(lx);
}

// fp16x2 pack: x in low half, y in high half
__device__ __forceinline__ unsigned packh2(float x, float y) {
    unsigned r;
    asm("cvt.rn.f16x2.f32 %0, %1, %2;" : "=r"(r) : "f"(y), "f"(x));
    return r;
}

// ldmatrix x4, non-transposed
__device__ __forceinline__ void ldsm4(unsigned r[4], unsigned addr) {
    asm volatile("ldmatrix.sync.aligned.m8n8.x4.shared.b16 {%0,%1,%2,%3}, [%4];"
        : "=r"(r[0]), "=r"(r[1]), "=r"(r[2]), "=r"(r[3]) : "r"(addr));
}
// ldmatrix x4, transposed (b16)
__device__ __forceinline__ void ldsm4t(unsigned r[4], unsigned addr) {
    asm volatile("ldmatrix.sync.aligned.m8n8.x4.trans.shared.b16 {%0,%1,%2,%3}, [%4];"
        : "=r"(r[0]), "=r"(r[1]), "=r"(r[2]), "=r"(r[3]) : "r"(addr));
}

// mma.sync m16n8k16 bf16 -> f32 accum
__device__ __forceinline__ void mma16816(float c[4], const unsigned a[4],
                                         const unsigned b[2]) {
    asm volatile(
        "mma.sync.aligned.m16n8k16.row.col.f32.bf16.bf16.f32 "
        "{%0,%1,%2,%3}, {%4,%5,%6,%7}, {%8,%9}, {%0,%1,%2,%3};"
        : "+f"(c[0]), "+f"(c[1]), "+f"(c[2]), "+f"(c[3])
        : "r"(a[0]), "r"(a[1]), "r"(a[2]), "r"(a[3]), "r"(b[0]), "r"(b[1]));
}
// mma.sync m16n8k16 fp16 -> f32 accum
__device__ __forceinline__ void mma16816h(float c[4], const unsigned a[4],
                                          const unsigned b[2]) {
    asm volatile(
        "mma.sync.aligned.m16n8k16.row.col.f32.f16.f16.f32 "
        "{%0,%1,%2,%3}, {%4,%5,%6,%7}, {%8,%9}, {%0,%1,%2,%3};"
        : "+f"(c[0]), "+f"(c[1]), "+f"(c[2]), "+f"(c[3])
        : "r"(a[0]), "r"(a[1]), "r"(a[2]), "r"(a[3]), "r"(b[0]), "r"(b[1]));
}

// cp.async 16B, L1-bypass
__device__ __forceinline__ void cp16(unsigned dst, const unsigned* src) {
    asm volatile("cp.async.cg.shared.global [%0], [%1], 16;"
        :: "r"(dst), "l"(src));
}
#define CP_COMMIT() asm volatile("cp.async.commit_group;" ::: "memory")
#define CP_WAIT(n)  asm volatile("cp.async.wait_group %0;" :: "n"(n) : "memory")

// ===========================================================================
// Kernel 0: W pre-split (fp32 -> packed bf16 hi/lo), 192 x 1024 elements.
// ===========================================================================
__global__ __launch_bounds__(256) void wsplit_kernel(
    const float* __restrict__ Wq, const float* __restrict__ Wk,
    const float* __restrict__ Wv)
{
    int idx = blockIdx.x * 256 + threadIdx.x;   // 0..98303 (uint pairs)
    int row = idx >> 9;                         // 0..191
    int d2 = idx & 511;
    const float* W = (row < 64) ? Wq : (row < 128 ? Wk : Wv);
    int r = row & 63;
    float2 f = *(const float2*)&W[(size_t)r * NC + d2 * 2];
    unsigned hp, lp;
    split2(f.x, f.y, hp, lp);
    g_whi[idx] = hp;
    g_wlo[idx] = lp;
}

// ===========================================================================
// Kernel 1: fused QKV projection on mma.sync (bf16x3).
// Epilogue writes: Q/K pre-split bf16 hi/lo (Q scaled by 8*log2e),
// V packed single fp16.
// grid = 128 (M tiles of 128), 256 threads (8 warps = 4 M x 2 N-halves of 96).
// ===========================================================================
#define QK_XHI 0            // 128 x 72 bf16 = 18432 B
#define QK_XLO 18432
#define QK_WHI 36864        // 192 x 72 bf16 = 27648 B
#define QK_WLO 64512
#define QK_TOTAL 92160

__global__ __launch_bounds__(256, 1) void qkv_kernel(
    const float* __restrict__ x,
    const float* __restrict__ bq, const float* __restrict__ bk,
    const float* __restrict__ bv)
{
    extern __shared__ char sm[];
    unsigned smb = smem_to_u32(sm);

    int tid = threadIdx.x;
    int lane = tid & 31;
    int wid = tid >> 5;
    int mw = wid & 3;           // rows mw*32 .. +31
    int nh = wid >> 2;          // cols nh*96 .. +95
    int row0 = blockIdx.x * 128;

    float cO[2][12][4] = {};

    for (int kc = 0; kc < 16; kc++) {
        if (kc) __syncthreads();            // prior chunk's reads done

        // ---- stage X chunk (128 rows x 64 k), split to hi/lo ----
#pragma unroll
        for (int i = 0; i < 16; i++) {
            int idx = tid + i * 256;        // 4096 float2s
            int rr = idx >> 5;
            int d2 = idx & 31;
            float2 f = *(const float2*)&x[(size_t)(row0 + rr) * NC + kc * 64 + d2 * 2];
            unsigned hp, lp;
            split2(f.x, f.y, hp, lp);
            *(unsigned*)(sm + QK_XHI + rr * 144 + d2 * 4) = hp;
            *(unsigned*)(sm + QK_XLO + rr * 144 + d2 * 4) = lp;
        }
        // ---- stage W chunk (192 rows x 64 k), already split ----
#pragma unroll
        for (int i = 0; i < 24; i++) {
            int idx = tid + i * 256;        // 6144 uints
            int rr = idx >> 5;
            int d2 = idx & 31;
            int gsrc = rr * 512 + kc * 32 + d2;
            *(unsigned*)(sm + QK_WHI + rr * 144 + d2 * 4) = g_whi[gsrc];
            *(unsigned*)(sm + QK_WLO + rr * 144 + d2 * 4) = g_wlo[gsrc];
        }
        __syncthreads();

        // ---- MMA: warp tile 32 rows x 96 cols, bf16x3 ----
#pragma unroll
        for (int ks = 0; ks < 4; ks++) {
            unsigned ah[2][4], al[2][4];
#pragma unroll
            for (int mi = 0; mi < 2; mi++) {
                unsigned xoff = (unsigned)((mw * 32 + mi * 16 + (lane & 15)) * 144 +
                                           (ks * 16 + (lane >> 4) * 8) * 2);
                ldsm4(ah[mi], smb + QK_XHI + xoff);
                ldsm4(al[mi], smb + QK_XLO + xoff);
            }
            unsigned bh[12][2], bl[12][2];
#pragma unroll
            for (int np = 0; np < 6; np++) {
                unsigned woff = (unsigned)((nh * 96 + np * 16 + (lane >> 4) * 8 +
                                            (lane & 7)) * 144 +
                                           (ks * 16 + ((lane >> 3) & 1) * 8) * 2);
                unsigned r[4];
                ldsm4(r, smb + QK_WHI + woff);
                bh[2 * np][0] = r[0]; bh[2 * np][1] = r[1];
                bh[2 * np + 1][0] = r[2]; bh[2 * np + 1][1] = r[3];
                ldsm4(r, smb + QK_WLO + woff);
                bl[2 * np][0] = r[0]; bl[2 * np][1] = r[1];
                bl[2 * np + 1][0] = r[2]; bl[2 * np + 1][1] = r[3];
            }
#pragma unroll
            for (int mi = 0; mi < 2; mi++)
#pragma unroll
                for (int nj = 0; nj < 12; nj++) {
                    mma16816(cO[mi][nj], ah[mi], bh[nj]);
                    mma16816(cO[mi][nj], ah[mi], bl[nj]);
                    mma16816(cO[mi][nj], al[mi], bh[nj]);
                }
        }
    }

    // ---- epilogue: add bias; Q/K -> bf16 hi/lo split, V -> single fp16 ----
    const float QSCALE = 8.0f * 1.4426950408889634f;   // fold exp2 domain into Q
#pragma unroll
    for (int mi = 0; mi < 2; mi++)
#pragma unroll
        for (int nj = 0; nj < 12; nj++) {
            int gc = nh * 96 + nj * 8 + 2 * (lane & 3);   // global col, even
            int r0 = row0 + mw * 32 + mi * 16 + (lane >> 2);
            if (gc < 128) {
                unsigned *dhi, *dlo;
                const float* bias;
                int col;
                float scale;
                if (gc < 64) { dhi = g_qhi; dlo = g_qlo; bias = bq; col = gc; scale = QSCALE; }
                else         { dhi = g_khi; dlo = g_klo; bias = bk; col = gc - 64; scale = 1.0f; }
                float b0 = __ldg(&bias[col]);
                float b1 = __ldg(&bias[col + 1]);
                unsigned hp, lp;
                split2((cO[mi][nj][0] + b0) * scale, (cO[mi][nj][1] + b1) * scale, hp, lp);
                dhi[(size_t)r0 * 32 + col / 2] = hp;
                dlo[(size_t)r0 * 32 + col / 2] = lp;
                split2((cO[mi][nj][2] + b0) * scale, (cO[mi][nj][3] + b1) * scale, hp, lp);
                dhi[(size_t)(r0 + 8) * 32 + col / 2] = hp;
                dlo[(size_t)(r0 + 8) * 32 + col / 2] = lp;
            } else {
                int col = gc - 128;
                float b0 = __ldg(&bv[col]);
                float b1 = __ldg(&bv[col + 1]);
                g_vh[(size_t)r0 * 32 + col / 2] =
                    packh2(cO[mi][nj][0] + b0, cO[mi][nj][1] + b1);
                g_vh[(size_t)(r0 + 8) * 32 + col / 2] =
                    packh2(cO[mi][nj][2] + b0, cO[mi][nj][3] + b1);
            }
        }
}

// ===========================================================================
// Kernel 2: flash attention on mma.sync (kv-split partials).
// S = QK^T in bf16x3 (3 MMAs); PV in single fp16 (1 MMA).
// grid = (NT/64, NB, NSPLIT), 128 threads (4 warps; warp w owns q rows
// w*16..+15, full 64 kv cols -> softmax warp-local). 3 CTAs/SM;
// cp.async double buffer. Writes unnormalized partial O + (m, l).
// ===========================================================================
#define AT_QHI 0                 // 64 x 144 B = 9216
#define AT_QLO 9216
#define AT_KV  18432             // 2 stages x 27648 (khi, klo, vh @ 9216 each)
#define AT_STG 27648
#define AT_TOTAL 73728
#define NKT (NT / BK / NSPLIT)   // kv tiles per split = 32

__device__ __forceinline__ void stage_kv(unsigned smb, int s, int tid, int kt,
    const unsigned* khi, const unsigned* klo, const unsigned* vh)
{
    unsigned base = smb + AT_KV + s * AT_STG;
    const unsigned* gs[3] = {khi, klo, vh};
#pragma unroll
    for (int a = 0; a < 3; a++)
#pragma unroll
        for (int i = 0; i < 4; i++) {
            int idx = tid + i * 128;      // 0..511
            int rr = idx >> 3;
            int c = idx & 7;
            cp16(base + a * 9216 + rr * 144 + c * 16,
                 gs[a] + (size_t)(kt * BK + rr) * 32 + c * 4);
        }
}

__global__ __launch_bounds__(128, 3) void attn_kernel()
{
    extern __shared__ char sm[];
    unsigned smb = smem_to_u32(sm);

    int tid = threadIdx.x;
    int lane = tid & 31;
    int w = tid >> 5;            // warp 0..3: q rows w*16 .. +15
    int b = blockIdx.y;
    int z = blockIdx.z;          // kv split index
    int q0 = blockIdx.x * BQ;
    int mrow = w * 16;
    int kt0 = z * NKT;

    const unsigned* qhi = g_qhi + (size_t)b * NT * 32;
    const unsigned* qlo = g_qlo + (size_t)b * NT * 32;
    const unsigned* khi = g_khi + (size_t)b * NT * 32;
    const unsigned* klo = g_klo + (size_t)b * NT * 32;
    const unsigned* vh  = g_vh  + (size_t)b * NT * 32;

    // ---- stage Q (already split & scaled), then first K/V tile ----
    {
        const unsigned* qs[2] = {qhi, qlo};
#pragma unroll
        for (int a = 0; a < 2; a++)
#pragma unroll
            for (int i = 0; i < 4; i++) {
                int idx = tid + i * 128;
                int rr = idx >> 3;
                int c = idx & 7;
                cp16(smb + a * 9216 + rr * 144 + c * 16,
                     qs[a] + (size_t)(q0 + rr) * 32 + c * 4);
            }
    }
    CP_COMMIT();                                   // G0 = Q
    stage_kv(smb, 0, tid, kt0, khi, klo, vh);
    CP_COMMIT();                                   // G1 = KV0
    CP_WAIT(1);                                    // Q done
    __syncthreads();

    // ---- hoist Q fragments into registers (once) ----
    unsigned qfh[4][4], qfl[4][4];
#pragma unroll
    for (int ks = 0; ks < 4; ks++) {
        unsigned qoff = (unsigned)((mrow + (lane & 15)) * 144 +
                                   (ks * 16 + (lane >> 4) * 8) * 2);
        ldsm4(qfh[ks], smb + AT_QHI + qoff);
        ldsm4(qfl[ks], smb + AT_QLO + qoff);
    }

    float cO[8][4] = {};
    float m_[2] = {-1e30f, -1e30f};
    float l_[2] = {0.0f, 0.0f};

    for (int ki = 0; ki < NKT; ki++) {
        int s = ki & 1;
        unsigned kb = smb + AT_KV + s * AT_STG;          // khi base
        if (ki + 1 < NKT) {
            stage_kv(smb, s ^ 1, tid, kt0 + ki + 1, khi, klo, vh);
            CP_COMMIT();
            CP_WAIT(1);
        } else {
            CP_WAIT(0);
        }
        __syncthreads();

        // ---- S = Q K^T, bf16x3: warp tile 16 rows x 64 cols ----
        float cS[8][4] = {};
#pragma unroll
        for (int ks = 0; ks < 4; ks++) {  // d k-chunks of 16
            unsigned bh[8][2], bl[8][2];
#pragma unroll
            for (int np = 0; np < 4; np++) {
                unsigned koff = (unsigned)((np * 16 + (lane >> 4) * 8 +
                                            (lane & 7)) * 144 +
                                           (ks * 16 + ((lane >> 3) & 1) * 8) * 2);
                unsigned r[4];
                ldsm4(r, kb + koff);
                bh[2 * np][0] = r[0]; bh[2 * np][1] = r[1];
                bh[2 * np + 1][0] = r[2]; bh[2 * np + 1][1] = r[3];
                ldsm4(r, kb + 9216 + koff);
                bl[2 * np][0] = r[0]; bl[2 * np][1] = r[1];
                bl[2 * np + 1][0] = r[2]; bl[2 * np + 1][1] = r[3];
            }
#pragma unroll
            for (int nj = 0; nj < 8; nj++) {
                mma16816(cS[nj], qfh[ks], bh[nj]);
                mma16816(cS[nj], qfh[ks], bl[nj]);
                mma16816(cS[nj], qfl[ks], bh[nj]);
            }
        }

        // ---- warp-local online softmax (exp2 domain) ----
        float alpha[2];
#pragma unroll
        for (int j = 0; j < 2; j++) {
            float v = -1e30f;
#pragma unroll
            for (int nj = 0; nj < 8; nj++)
                v = fmaxf(v, fmaxf(cS[nj][2 * j], cS[nj][2 * j + 1]));
            v = fmaxf(v, __shfl_xor_sync(0xffffffffu, v, 1));
            v = fmaxf(v, __shfl_xor_sync(0xffffffffu, v, 2));
            float mn = fmaxf(m_[j], v);
            alpha[j] = ex2(m_[j] - mn);
            m_[j] = mn;
        }
#pragma unroll
        for (int nj = 0; nj < 8; nj++) {
            cO[nj][0] *= alpha[0];
            cO[nj][1] *= alpha[0];
            cO[nj][2] *= alpha[1];
            cO[nj][3] *= alpha[1];
        }
#pragma unroll
        for (int j = 0; j < 2; j++) {
            float s2 = 0.0f;
#pragma unroll
            for (int nj = 0; nj < 8; nj++) {
                float e0 = ex2(cS[nj][2 * j] - m_[j]);
                float e1 = ex2(cS[nj][2 * j + 1] - m_[j]);
                cS[nj][2 * j] = e0;
                cS[nj][2 * j + 1] = e1;
                s2 += e0 + e1;
            }
            s2 += __shfl_xor_sync(0xffffffffu, s2, 1);
            s2 += __shfl_xor_sync(0xffffffffu, s2, 2);
            l_[j] = l_[j] * alpha[j] + s2;
        }

        // ---- convert P (c-frag -> a-frag identity), single fp16 ----
        unsigned ph[4][4];                // [ks2][reg], k = 64 kv tokens
#pragma unroll
        for (int ks2 = 0; ks2 < 4; ks2++) {
            ph[ks2][0] = packh2(cS[2 * ks2][0],     cS[2 * ks2][1]);
            ph[ks2][1] = packh2(cS[2 * ks2][2],     cS[2 * ks2][3]);
            ph[ks2][2] = packh2(cS[2 * ks2 + 1][0], cS[2 * ks2 + 1][1]);
            ph[ks2][3] = packh2(cS[2 * ks2 + 1][2], cS[2 * ks2 + 1][3]);
        }

        // ---- O += P V (full k = 64), single fp16 MMA ----
#pragma unroll
        for (int ks2 = 0; ks2 < 4; ks2++) {
            unsigned vhf[4][4];              // [npj][reg]
#pragma unroll
            for (int npj = 0; npj < 4; npj++) {
                unsigned voff = (unsigned)((ks2 * 16 + ((lane >> 3) & 1) * 8 +
                                            (lane & 7)) * 144 +
                                           (npj * 16 + (lane >> 4) * 8) * 2);
                ldsm4t(vhf[npj], kb + 18432 + voff);
            }
#pragma unroll
            for (int nj = 0; nj < 8; nj++)
                mma16816h(cO[nj], ph[ks2], &vhf[nj >> 1][(nj & 1) * 2]);
        }
        __syncthreads();   // stage-s readers done before ki+2 overwrites it
    }

    // ---- epilogue: write unnormalized partial O + (m, l) ----
    int r0 = q0 + mrow + (lane >> 2);
    size_t pbase = ((size_t)(z * NB + b) * NT + r0) * ND;
#pragma unroll
    for (int nj = 0; nj < 8; nj++) {
        int c0 = nj * 8 + 2 * (lane & 3);
        *(float2*)&g_po[pbase + c0] = make_float2(cO[nj][0], cO[nj][1]);
        *(float2*)&g_po[pbase + (size_t)8 * ND + c0] = make_float2(cO[nj][2], cO[nj][3]);
    }
    if ((lane & 3) == 0) {
        size_t mb = (size_t)(z * NB + b) * NT + r0;
        g_pm[mb] = m_[0];
        g_pl[mb] = l_[0];
        g_pm[mb + 8] = m_[1];
        g_pl[mb + 8] = l_[1];
    }
}

// ===========================================================================
// Kernel 3: combine the NSPLIT kv partials, normalize, store output.
// One thread per 4 output elements (float4). grid = NB*NT*16/256 = 1024.
// ===========================================================================
__global__ __launch_bounds__(256) void combine_kernel(float* __restrict__ out)
{
    int idx = blockIdx.x * 256 + threadIdx.x;   // 0 .. NB*NT*16-1
    int c4 = (idx & 15) * 4;                    // col 0..60
    int row = (idx >> 4) & (NT - 1);
    int b = idx >> 16;                          // NT*16 = 65536 per batch

    size_t m0i = (size_t)b * NT + row;
    size_t m1i = (size_t)(NB + b) * NT + row;
    float m0 = g_pm[m0i], m1 = g_pm[m1i];
    float l0 = g_pl[m0i], l1 = g_pl[m1i];
    float M = fmaxf(m0, m1);
    float a0 = ex2(m0 - M), a1 = ex2(m1 - M);
    float inv = 1.0f / (l0 * a0 + l1 * a1);

    float4 O0 = *(const float4*)&g_po[m0i * ND + c4];
    float4 O1 = *(const float4*)&g_po[m1i * ND + c4];
    float4 r;
    r.x = (O0.x * a0 + O1.x * a1) * inv;
    r.y = (O0.y * a0 + O1.y * a1) * inv;
    r.z = (O0.z * a0 + O1.z * a1) * inv;
    r.w = (O0.w * a0 + O1.w * a1) * inv;
    *(float4*)&out[((size_t)b * NT + row) * ND + c4] = r;
}

// ===========================================================================
extern "C" void kernel_launch(void* const* d_in, const int* in_sizes, int n_in,
                              void* d_out, int out_size)
{
    (void)in_sizes; (void)n_in; (void)out_size;
    const float* x  = (const float*)d_in[0];
    const float* Wq = (const float*)d_in[1];
    const float* bq = (const float*)d_in[2];
    const float* Wk = (const float*)d_in[3];
    const float* bk = (const float*)d_in[4];
    const float* Wv = (const float*)d_in[5];
    const float* bv = (const float*)d_in[6];
    float* out = (float*)d_out;

    // 0: pre-split W into bf16 hi/lo (192*512 uint pairs)
    wsplit_kernel<<<384, 256>>>(Wq, Wk, Wv);

    // 1: fused QKV projection (tensor cores); Q/K split bf16, V fp16
    cudaFuncSetAttribute(qkv_kernel,
                         cudaFuncAttributeMaxDynamicSharedMemorySize,
                         QK_TOTAL);
    qkv_kernel<<<(NB * NT) / 128, 256, QK_TOTAL>>>(x, bq, bk, bv);

    // 2: flash attention kv-split partials (3 CTAs/SM, 512 CTAs)
    cudaFuncSetAttribute(attn_kernel,
                         cudaFuncAttributeMaxDynamicSharedMemorySize,
                         AT_TOTAL);
    attn_kernel<<<dim3(NT / BQ, NB, NSPLIT), 128, AT_TOTAL>>>();

    // 3: combine partials, normalize
    combine_kernel<<<NB * NT * 16 / 256, 256>>>(out);
}

// round 16
// speedup vs baseline: 1.0443x; 1.0443x over previous
#include <cuda_runtime.h>
#include <cuda_bf16.h>
#include <cuda_fp16.h>
#include <math.h>

// Problem constants
#define NB 4
#define NT 4096
#define NC 1024
#define ND 64
#define BQ 64           // q rows per CTA (attention)
#define BK 64           // kv tokens per tile (attention)

// Pre-split projections. Q/K: packed bf16x2 hi/lo (32 uints per token row),
// Q pre-scaled by 8*log2(e). V: packed fp16x2 single (32 uints per row).
__device__ unsigned g_qhi[NB * NT * 32];
__device__ unsigned g_qlo[NB * NT * 32];
__device__ unsigned g_khi[NB * NT * 32];
__device__ unsigned g_klo[NB * NT * 32];
__device__ unsigned g_vh [NB * NT * 32];
// Pre-split W (packed bf16x2 hi/lo): rows 0-63 Wq, 64-127 Wk, 128-191 Wv
__device__ unsigned g_whi[192 * 512];
__device__ unsigned g_wlo[192 * 512];

// ===========================================================================
// Helpers
// ===========================================================================
__device__ __forceinline__ unsigned smem_to_u32(const void* p) {
    unsigned a;
    asm("{ .reg .u64 t; cvta.to.shared.u64 t, %1; cvt.u32.u64 %0, t; }"
        : "=r"(a) : "l"(p));
    return a;
}

__device__ __forceinline__ float ex2(float x) {
    float y;
    asm("ex2.approx.ftz.f32 %0, %1;" : "=f"(y) : "f"(x));
    return y;
}

// bf16 hi/lo split of a float pair, packed little-endian (x in low half)
__device__ __forceinline__ void split2(float x, float y, unsigned& hp, unsigned& lp) {
    __nv_bfloat16 hx = __float2bfloat16(x);
    __nv_bfloat16 hy = __float2bfloat16(y);
    float rx = x - __bfloat162float(hx);
    float ry = y - __bfloat162float(hy);
    __nv_bfloat16 lx = __float2bfloat16(rx);
    __nv_bfloat16 ly = __float2bfloat16(ry);
    hp = ((unsigned)__bfloat16_as_ushort(hy) << 16) | __bfloat16_as_ushort(hx);
    lp = ((unsigned)__bfloat16_as_ushort(ly) << 16) | __bfloat16_as_ushort(lx);
}

// fp16x2 pack: x in low half, y in high half
__device__ __forceinline__ unsigned packh2(float x, float y) {
    unsigned r;
    asm("cvt.rn.f16x2.f32 %0, %1, %2;" : "=r"(r) : "f"(y), "f"(x));
    return r;
}

// ldmatrix x4, non-transposed
__device__ __forceinline__ void ldsm4(unsigned r[4], unsigned addr) {
    asm volatile("ldmatrix.sync.aligned.m8n8.x4.shared.b16 {%0,%1,%2,%3}, [%4];"
        : "=r"(r[0]), "=r"(r[1]), "=r"(r[2]), "=r"(r[3]) : "r"(addr));
}
// ldmatrix x4, transposed (b16)
__device__ __forceinline__ void ldsm4t(unsigned r[4], unsigned addr) {
    asm volatile("ldmatrix.sync.aligned.m8n8.x4.trans.shared.b16 {%0,%1,%2,%3}, [%4];"
        : "=r"(r[0]), "=r"(r[1]), "=r"(r[2]), "=r"(r[3]) : "r"(addr));
}

// mma.sync m16n8k16 bf16 -> f32 accum
__device__ __forceinline__ void mma16816(float c[4], const unsigned a[4],
                                         const unsigned b[2]) {
    asm volatile(
        "mma.sync.aligned.m16n8k16.row.col.f32.bf16.bf16.f32 "
        "{%0,%1,%2,%3}, {%4,%5,%6,%7}, {%8,%9}, {%0,%1,%2,%3};"
        : "+f"(c[0]), "+f"(c[1]), "+f"(c[2]), "+f"(c[3])
        : "r"(a[0]), "r"(a[1]), "r"(a[2]), "r"(a[3]), "r"(b[0]), "r"(b[1]));
}
// mma.sync m16n8k16 fp16 -> f32 accum
__device__ __forceinline__ void mma16816h(float c[4], const unsigned a[4],
                                          const unsigned b[2]) {
    asm volatile(
        "mma.sync.aligned.m16n8k16.row.col.f32.f16.f16.f32 "
        "{%0,%1,%2,%3}, {%4,%5,%6,%7}, {%8,%9}, {%0,%1,%2,%3};"
        : "+f"(c[0]), "+f"(c[1]), "+f"(c[2]), "+f"(c[3])
        : "r"(a[0]), "r"(a[1]), "r"(a[2]), "r"(a[3]), "r"(b[0]), "r"(b[1]));
}

// cp.async 16B, L1-bypass
__device__ __forceinline__ void cp16(unsigned dst, const unsigned* src) {
    asm volatile("cp.async.cg.shared.global [%0], [%1], 16;"
        :: "r"(dst), "l"(src));
}
#define CP_COMMIT() asm volatile("cp.async.commit_group;" ::: "memory")
#define CP_WAIT(n)  asm volatile("cp.async.wait_group %0;" :: "n"(n) : "memory")

// ===========================================================================
// Kernel 0: W pre-split (fp32 -> packed bf16 hi/lo), 192 x 1024 elements.
// ===========================================================================
__global__ __launch_bounds__(256) void wsplit_kernel(
    const float* __restrict__ Wq, const float* __restrict__ Wk,
    const float* __restrict__ Wv)
{
    int idx = blockIdx.x * 256 + threadIdx.x;   // 0..98303 (uint pairs)
    int row = idx >> 9;                         // 0..191
    int d2 = idx & 511;
    const float* W = (row < 64) ? Wq : (row < 128 ? Wk : Wv);
    int r = row & 63;
    float2 f = *(const float2*)&W[(size_t)r * NC + d2 * 2];
    unsigned hp, lp;
    split2(f.x, f.y, hp, lp);
    g_whi[idx] = hp;
    g_wlo[idx] = lp;
}

// ===========================================================================
// Kernel 1: fused QKV projection on mma.sync (bf16x3), software-pipelined.
// Double-buffered: W chunks prefetched via cp.async; X chunks prefetched to
// registers before the MMA loop, split+stored after. One barrier per chunk.
// Epilogue writes: Q/K pre-split bf16 hi/lo (Q scaled by 8*log2e), V fp16.
// grid = 128 (M tiles of 128), 256 threads (8 warps = 4 M x 2 N-halves of 96).
// ===========================================================================
#define QK_X0 0             // X buf: hi at +0, lo at +18432 (128 x 144 each)
#define QK_X1 36864
#define QK_W0 73728         // W buf: hi at +0, lo at +27648 (192 x 144 each)
#define QK_W1 129024
#define QK_TOTAL 184320

__device__ __forceinline__ void qk_stage_w(unsigned dstbase, int tid, int kc) {
#pragma unroll
    for (int i = 0; i < 6; i++) {
        int idx = tid + i * 256;     // 0..1535
        int rr = idx >> 3;           // row 0..191
        int c = idx & 7;
        cp16(dstbase + rr * 144 + c * 16, g_whi + rr * 512 + kc * 32 + c * 4);
        cp16(dstbase + 27648 + rr * 144 + c * 16, g_wlo + rr * 512 + kc * 32 + c * 4);
    }
}

__device__ __forceinline__ void qk_load_x(float2* xr, const float* x,
                                          int row0, int kc, int tid) {
#pragma unroll
    for (int i = 0; i < 16; i++) {
        int idx = tid + i * 256;
        int rr = idx >> 5;
        int d2 = idx & 31;
        xr[i] = *(const float2*)&x[(size_t)(row0 + rr) * NC + kc * 64 + d2 * 2];
    }
}

__device__ __forceinline__ void qk_store_x(char* sm, unsigned base,
                                           const float2* xr, int tid) {
#pragma unroll
    for (int i = 0; i < 16; i++) {
        int idx = tid + i * 256;
        int rr = idx >> 5;
        int d2 = idx & 31;
        unsigned hp, lp;
        split2(xr[i].x, xr[i].y, hp, lp);
        *(unsigned*)(sm + base + rr * 144 + d2 * 4) = hp;
        *(unsigned*)(sm + base + 18432 + rr * 144 + d2 * 4) = lp;
    }
}

__global__ __launch_bounds__(256, 1) void qkv_kernel(
    const float* __restrict__ x,
    const float* __restrict__ bq, const float* __restrict__ bk,
    const float* __restrict__ bv)
{
    extern __shared__ char sm[];
    unsigned smb = smem_to_u32(sm);

    int tid = threadIdx.x;
    int lane = tid & 31;
    int wid = tid >> 5;
    int mw = wid & 3;           // rows mw*32 .. +31
    int nh = wid >> 2;          // cols nh*96 .. +95
    int row0 = blockIdx.x * 128;

    float cO[2][12][4] = {};
    float2 xr[16];

    // ---- prologue: stage chunk 0 ----
    qk_load_x(xr, x, row0, 0, tid);
    qk_stage_w(smb + QK_W0, tid, 0);
    CP_COMMIT();
    qk_store_x(sm, QK_X0, xr, tid);
    CP_WAIT(0);
    __syncthreads();

    for (int kc = 0; kc < 16; kc++) {
        int cur = kc & 1;
        unsigned xb = smb + (cur ? QK_X1 : QK_X0);
        unsigned wb = smb + (cur ? QK_W1 : QK_W0);

        if (kc < 15) {
            // prefetch next chunk: W via cp.async, X into registers
            qk_stage_w(smb + (cur ? QK_W0 : QK_W1), tid, kc + 1);
            CP_COMMIT();
            qk_load_x(xr, x, row0, kc + 1, tid);
        }

        // ---- MMA: warp tile 32 rows x 96 cols, bf16x3 ----
#pragma unroll
        for (int ks = 0; ks < 4; ks++) {
            unsigned ah[2][4], al[2][4];
#pragma unroll
            for (int mi = 0; mi < 2; mi++) {
                unsigned xoff = (unsigned)((mw * 32 + mi * 16 + (lane & 15)) * 144 +
                                           (ks * 16 + (lane >> 4) * 8) * 2);
                ldsm4(ah[mi], xb + xoff);
                ldsm4(al[mi], xb + 18432 + xoff);
            }
            unsigned bh[12][2], bl[12][2];
#pragma unroll
            for (int np = 0; np < 6; np++) {
                unsigned woff = (unsigned)((nh * 96 + np * 16 + (lane >> 4) * 8 +
                                            (lane & 7)) * 144 +
                                           (ks * 16 + ((lane >> 3) & 1) * 8) * 2);
                unsigned r[4];
                ldsm4(r, wb + woff);
                bh[2 * np][0] = r[0]; bh[2 * np][1] = r[1];
                bh[2 * np + 1][0] = r[2]; bh[2 * np + 1][1] = r[3];
                ldsm4(r, wb + 27648 + woff);
                bl[2 * np][0] = r[0]; bl[2 * np][1] = r[1];
                bl[2 * np + 1][0] = r[2]; bl[2 * np + 1][1] = r[3];
            }
#pragma unroll
            for (int mi = 0; mi < 2; mi++)
#pragma unroll
                for (int nj = 0; nj < 12; nj++) {
                    mma16816(cO[mi][nj], ah[mi], bh[nj]);
                    mma16816(cO[mi][nj], ah[mi], bl[nj]);
                    mma16816(cO[mi][nj], al[mi], bh[nj]);
                }
        }

        if (kc < 15) {
            // write prefetched X into the alternate buffer (read 2 chunks ago)
            qk_store_x(sm, cur ? QK_X0 : QK_X1, xr, tid);
            CP_WAIT(0);
        }
        __syncthreads();
    }

    // ---- epilogue: add bias; Q/K -> bf16 hi/lo split, V -> single fp16 ----
    const float QSCALE = 8.0f * 1.4426950408889634f;   // fold exp2 domain into Q
#pragma unroll
    for (int mi = 0; mi < 2; mi++)
#pragma unroll
        for (int nj = 0; nj < 12; nj++) {
            int gc = nh * 96 + nj * 8 + 2 * (lane & 3);   // global col, even
            int r0 = row0 + mw * 32 + mi * 16 + (lane >> 2);
            if (gc < 128) {
                unsigned *dhi, *dlo;
                const float* bias;
                int col;
                float scale;
                if (gc < 64) { dhi = g_qhi; dlo = g_qlo; bias = bq; col = gc; scale = QSCALE; }
                else         { dhi = g_khi; dlo = g_klo; bias = bk; col = gc - 64; scale = 1.0f; }
                float b0 = __ldg(&bias[col]);
                float b1 = __ldg(&bias[col + 1]);
                unsigned hp, lp;
                split2((cO[mi][nj][0] + b0) * scale, (cO[mi][nj][1] + b1) * scale, hp, lp);
                dhi[(size_t)r0 * 32 + col / 2] = hp;
                dlo[(size_t)r0 * 32 + col / 2] = lp;
                split2((cO[mi][nj][2] + b0) * scale, (cO[mi][nj][3] + b1) * scale, hp, lp);
                dhi[(size_t)(r0 + 8) * 32 + col / 2] = hp;
                dlo[(size_t)(r0 + 8) * 32 + col / 2] = lp;
            } else {
                int col = gc - 128;
                float b0 = __ldg(&bv[col]);
                float b1 = __ldg(&bv[col + 1]);
                g_vh[(size_t)r0 * 32 + col / 2] =
                    packh2(cO[mi][nj][0] + b0, cO[mi][nj][1] + b1);
                g_vh[(size_t)(r0 + 8) * 32 + col / 2] =
                    packh2(cO[mi][nj][2] + b0, cO[mi][nj][3] + b1);
            }
        }
}

// ===========================================================================
// Kernel 2: flash attention on mma.sync (identical to the 191.7us R13 version).
// S = QK^T in bf16x3 (3 MMAs); PV in single fp16 (1 MMA).
// grid = (NT/64, NB), 128 threads (4 warps; warp w owns q rows w*16..+15,
// full 64 kv cols -> softmax warp-local). 3 CTAs/SM; cp.async double buffer.
// ===========================================================================
#define AT_QHI 0                 // 64 x 144 B = 9216
#define AT_QLO 9216
#define AT_KV  18432             // 2 stages x 27648 (khi, klo, vh @ 9216 each)
#define AT_STG 27648
#define AT_TOTAL 73728

__device__ __forceinline__ void stage_kv(unsigned smb, int s, int tid, int kt,
    const unsigned* khi, const unsigned* klo, const unsigned* vh)
{
    unsigned base = smb + AT_KV + s * AT_STG;
    const unsigned* gs[3] = {khi, klo, vh};
#pragma unroll
    for (int a = 0; a < 3; a++)
#pragma unroll
        for (int i = 0; i < 4; i++) {
            int idx = tid + i * 128;      // 0..511
            int rr = idx >> 3;
            int c = idx & 7;
            cp16(base + a * 9216 + rr * 144 + c * 16,
                 gs[a] + (size_t)(kt * BK + rr) * 32 + c * 4);
        }
}

__global__ __launch_bounds__(128, 3) void attn_kernel(float* __restrict__ out)
{
    extern __shared__ char sm[];
    unsigned smb = smem_to_u32(sm);

    int tid = threadIdx.x;
    int lane = tid & 31;
    int w = tid >> 5;            // warp 0..3: q rows w*16 .. +15
    int b = blockIdx.y;
    int q0 = blockIdx.x * BQ;
    int mrow = w * 16;

    const unsigned* qhi = g_qhi + (size_t)b * NT * 32;
    const unsigned* qlo = g_qlo + (size_t)b * NT * 32;
    const unsigned* khi = g_khi + (size_t)b * NT * 32;
    const unsigned* klo = g_klo + (size_t)b * NT * 32;
    const unsigned* vh  = g_vh  + (size_t)b * NT * 32;

    // ---- stage Q (already split & scaled), then first K/V tile ----
    {
        const unsigned* qs[2] = {qhi, qlo};
#pragma unroll
        for (int a = 0; a < 2; a++)
#pragma unroll
            for (int i = 0; i < 4; i++) {
                int idx = tid + i * 128;
                int rr = idx >> 3;
                int c = idx & 7;
                cp16(smb + a * 9216 + rr * 144 + c * 16,
                     qs[a] + (size_t)(q0 + rr) * 32 + c * 4);
            }
    }
    CP_COMMIT();                                   // G0 = Q
    stage_kv(smb, 0, tid, 0, khi, klo, vh);
    CP_COMMIT();                                   // G1 = KV0
    CP_WAIT(1);                                    // Q done
    __syncthreads();

    // ---- hoist Q fragments into registers (once) ----
    unsigned qfh[4][4], qfl[4][4];
#pragma unroll
    for (int ks = 0; ks < 4; ks++) {
        unsigned qoff = (unsigned)((mrow + (lane & 15)) * 144 +
                                   (ks * 16 + (lane >> 4) * 8) * 2);
        ldsm4(qfh[ks], smb + AT_QHI + qoff);
        ldsm4(qfl[ks], smb + AT_QLO + qoff);
    }

    float cO[8][4] = {};
    float m_[2] = {-1e30f, -1e30f};
    float l_[2] = {0.0f, 0.0f};

    for (int kt = 0; kt < NT / BK; kt++) {
        int s = kt & 1;
        unsigned kb = smb + AT_KV + s * AT_STG;          // khi base
        if (kt + 1 < NT / BK) {
            stage_kv(smb, s ^ 1, tid, kt + 1, khi, klo, vh);
            CP_COMMIT();
            CP_WAIT(1);
        } else {
            CP_WAIT(0);
        }
        __syncthreads();

        // ---- S = Q K^T, bf16x3: warp tile 16 rows x 64 cols ----
        float cS[8][4] = {};
#pragma unroll
        for (int ks = 0; ks < 4; ks++) {  // d k-chunks of 16
            unsigned bh[8][2], bl[8][2];
#pragma unroll
            for (int np = 0; np < 4; np++) {
                unsigned koff = (unsigned)((np * 16 + (lane >> 4) * 8 +
                                            (lane & 7)) * 144 +
                                           (ks * 16 + ((lane >> 3) & 1) * 8) * 2);
                unsigned r[4];
                ldsm4(r, kb + koff);
                bh[2 * np][0] = r[0]; bh[2 * np][1] = r[1];
                bh[2 * np + 1][0] = r[2]; bh[2 * np + 1][1] = r[3];
                ldsm4(r, kb + 9216 + koff);
                bl[2 * np][0] = r[0]; bl[2 * np][1] = r[1];
                bl[2 * np + 1][0] = r[2]; bl[2 * np + 1][1] = r[3];
            }
#pragma unroll
            for (int nj = 0; nj < 8; nj++) {
                mma16816(cS[nj], qfh[ks], bh[nj]);
                mma16816(cS[nj], qfh[ks], bl[nj]);
                mma16816(cS[nj], qfl[ks], bh[nj]);
            }
        }

        // ---- warp-local online softmax (exp2 domain) ----
        float alpha[2];
#pragma unroll
        for (int j = 0; j < 2; j++) {
            float v = -1e30f;
#pragma unroll
            for (int nj = 0; nj < 8; nj++)
                v = fmaxf(v, fmaxf(cS[nj][2 * j], cS[nj][2 * j + 1]));
            v = fmaxf(v, __shfl_xor_sync(0xffffffffu, v, 1));
            v = fmaxf(v, __shfl_xor_sync(0xffffffffu, v, 2));
            float mn = fmaxf(m_[j], v);
            alpha[j] = ex2(m_[j] - mn);
            m_[j] = mn;
        }
#pragma unroll
        for (int nj = 0; nj < 8; nj++) {
            cO[nj][0] *= alpha[0];
            cO[nj][1] *= alpha[0];
            cO[nj][2] *= alpha[1];
            cO[nj][3] *= alpha[1];
        }
#pragma unroll
        for (int j = 0; j < 2; j++) {
            float s2 = 0.0f;
#pragma unroll
            for (int nj = 0; nj < 8; nj++) {
                float e0 = ex2(cS[nj][2 * j] - m_[j]);
                float e1 = ex2(cS[nj][2 * j + 1] - m_[j]);
                cS[nj][2 * j] = e0;
                cS[nj][2 * j + 1] = e1;
                s2 += e0 + e1;
            }
            s2 += __shfl_xor_sync(0xffffffffu, s2, 1);
            s2 += __shfl_xor_sync(0xffffffffu, s2, 2);
            l_[j] = l_[j] * alpha[j] + s2;
        }

        // ---- convert P (c-frag -> a-frag identity), single fp16 ----
        unsigned ph[4][4];                // [ks2][reg], k = 64 kv tokens
#pragma unroll
        for (int ks2 = 0; ks2 < 4; ks2++) {
            ph[ks2][0] = packh2(cS[2 * ks2][0],     cS[2 * ks2][1]);
            ph[ks2][1] = packh2(cS[2 * ks2][2],     cS[2 * ks2][3]);
            ph[ks2][2] = packh2(cS[2 * ks2 + 1][0], cS[2 * ks2 + 1][1]);
            ph[ks2][3] = packh2(cS[2 * ks2 + 1][2], cS[2 * ks2 + 1][3]);
        }

        // ---- O += P V (full k = 64), single fp16 MMA ----
#pragma unroll
        for (int ks2 = 0; ks2 < 4; ks2++) {
            unsigned vhf[4][4];              // [npj][reg]
#pragma unroll
            for (int npj = 0; npj < 4; npj++) {
                unsigned voff = (unsigned)((ks2 * 16 + ((lane >> 3) & 1) * 8 +
                                            (lane & 7)) * 144 +
                                           (npj * 16 + (lane >> 4) * 8) * 2);
                ldsm4t(vhf[npj], kb + 18432 + voff);
            }
#pragma unroll
            for (int nj = 0; nj < 8; nj++)
                mma16816h(cO[nj], ph[ks2], &vhf[nj >> 1][(nj & 1) * 2]);
        }
        __syncthreads();   // stage-s readers done before kt+2 overwrites it
    }

    // ---- epilogue: normalize, store (warp owns its rows outright) ----
    float i0 = 1.0f / l_[0];
    float i1 = 1.0f / l_[1];
    int r0 = q0 + mrow + (lane >> 2);
#pragma unroll
    for (int nj = 0; nj < 8; nj++) {
        int c0 = nj * 8 + 2 * (lane & 3);
        *(float2*)&out[((size_t)b * NT + r0) * ND + c0] =
            make_float2(cO[nj][0] * i0, cO[nj][1] * i0);
        *(float2*)&out[((size_t)b * NT + r0 + 8) * ND + c0] =
            make_float2(cO[nj][2] * i1, cO[nj][3] * i1);
    }
}

// ===========================================================================
extern "C" void kernel_launch(void* const* d_in, const int* in_sizes, int n_in,
                              void* d_out, int out_size)
{
    (void)in_sizes; (void)n_in; (void)out_size;
    const float* x  = (const float*)d_in[0];
    const float* Wq = (const float*)d_in[1];
    const float* bq = (const float*)d_in[2];
    const float* Wk = (const float*)d_in[3];
    const float* bk = (const float*)d_in[4];
    const float* Wv = (const float*)d_in[5];
    const float* bv = (const float*)d_in[6];
    float* out = (float*)d_out;

    // 0: pre-split W into bf16 hi/lo (192*512 uint pairs)
    wsplit_kernel<<<384, 256>>>(Wq, Wk, Wv);

    // 1: fused QKV projection (tensor cores, software-pipelined)
    cudaFuncSetAttribute(qkv_kernel,
                         cudaFuncAttributeMaxDynamicSharedMemorySize,
                         QK_TOTAL);
    qkv_kernel<<<(NB * NT) / 128, 256, QK_TOTAL>>>(x, bq, bk, bv);

    // 2: flash attention (tensor cores, 3 CTAs/SM, cp.async double buffer)
    cudaFuncSetAttribute(attn_kernel,
                         cudaFuncAttributeMaxDynamicSharedMemorySize,
                         AT_TOTAL);
    attn_kernel<<<dim3(NT / BQ, NB), 128, AT_TOTAL>>>(out);
}

// round 17
// speedup vs baseline: 1.1457x; 1.0971x over previous
#include <cuda_runtime.h>
#include <cuda_bf16.h>
#include <cuda_fp16.h>
#include <math.h>

// Problem constants
#define NB 4
#define NT 4096
#define NC 1024
#define ND 64
#define BQ 128          // q rows per CTA (attention): 4 warps x 32 rows
#define BK 64           // kv tokens per tile (attention)
#define NSPLIT 2        // kv-range splits

// Pre-split projections. Q/K: packed bf16x2 hi/lo (32 uints per token row),
// Q pre-scaled by 8*log2(e). V: packed fp16x2 single (32 uints per row).
__device__ unsigned g_qhi[NB * NT * 32];
__device__ unsigned g_qlo[NB * NT * 32];
__device__ unsigned g_khi[NB * NT * 32];
__device__ unsigned g_klo[NB * NT * 32];
__device__ unsigned g_vh [NB * NT * 32];
// Pre-split W (packed bf16x2 hi/lo): rows 0-63 Wq, 64-127 Wk, 128-191 Wv
__device__ unsigned g_whi[192 * 512];
__device__ unsigned g_wlo[192 * 512];
// KV-split partials: unnormalized O + per-row (m, l), exp2 domain
__device__ float g_po[NSPLIT * NB * NT * ND];
__device__ float g_pm[NSPLIT * NB * NT];
__device__ float g_pl[NSPLIT * NB * NT];

// ===========================================================================
// Helpers
// ===========================================================================
__device__ __forceinline__ unsigned smem_to_u32(const void* p) {
    unsigned a;
    asm("{ .reg .u64 t; cvta.to.shared.u64 t, %1; cvt.u32.u64 %0, t; }"
        : "=r"(a) : "l"(p));
    return a;
}

__device__ __forceinline__ float ex2(float x) {
    float y;
    asm("ex2.approx.ftz.f32 %0, %1;" : "=f"(y) : "f"(x));
    return y;
}

// bf16 hi/lo split of a float pair, packed little-endian (x in low half)
__device__ __forceinline__ void split2(float x, float y, unsigned& hp, unsigned& lp) {
    __nv_bfloat16 hx = __float2bfloat16(x);
    __nv_bfloat16 hy = __float2bfloat16(y);
    float rx = x - __bfloat162float(hx);
    float ry = y - __bfloat162float(hy);
    __nv_bfloat16 lx = __float2bfloat16(rx);
    __nv_bfloat16 ly = __float2bfloat16(ry);
    hp = ((unsigned)__bfloat16_as_ushort(hy) << 16) | __bfloat16_as_ushort(hx);
    lp = ((unsigned)__bfloat16_as_ushort(ly) << 16) | __bfloat16_as_ushort(lx);
}

// fp16x2 pack: x in low half, y in high half
__device__ __forceinline__ unsigned packh2(float x, float y) {
    unsigned r;
    asm("cvt.rn.f16x2.f32 %0, %1, %2;" : "=r"(r) : "f"(y), "f"(x));
    return r;
}

// ldmatrix x4, non-transposed
__device__ __forceinline__ void ldsm4(unsigned r[4], unsigned addr) {
    asm volatile("ldmatrix.sync.aligned.m8n8.x4.shared.b16 {%0,%1,%2,%3}, [%4];"
        : "=r"(r[0]), "=r"(r[1]), "=r"(r[2]), "=r"(r[3]) : "r"(addr));
}
// ldmatrix x4, transposed (b16)
__device__ __forceinline__ void ldsm4t(unsigned r[4], unsigned addr) {
    asm volatile("ldmatrix.sync.aligned.m8n8.x4.trans.shared.b16 {%0,%1,%2,%3}, [%4];"
        : "=r"(r[0]), "=r"(r[1]), "=r"(r[2]), "=r"(r[3]) : "r"(addr));
}

// mma.sync m16n8k16 bf16 -> f32 accum
__device__ __forceinline__ void mma16816(float c[4], const unsigned a[4],
                                         const unsigned b[2]) {
    asm volatile(
        "mma.sync.aligned.m16n8k16.row.col.f32.bf16.bf16.f32 "
        "{%0,%1,%2,%3}, {%4,%5,%6,%7}, {%8,%9}, {%0,%1,%2,%3};"
        : "+f"(c[0]), "+f"(c[1]), "+f"(c[2]), "+f"(c[3])
        : "r"(a[0]), "r"(a[1]), "r"(a[2]), "r"(a[3]), "r"(b[0]), "r"(b[1]));
}
// mma.sync m16n8k16 fp16 -> f32 accum
__device__ __forceinline__ void mma16816h(float c[4], const unsigned a[4],
                                          const unsigned b[2]) {
    asm volatile(
        "mma.sync.aligned.m16n8k16.row.col.f32.f16.f16.f32 "
        "{%0,%1,%2,%3}, {%4,%5,%6,%7}, {%8,%9}, {%0,%1,%2,%3};"
        : "+f"(c[0]), "+f"(c[1]), "+f"(c[2]), "+f"(c[3])
        : "r"(a[0]), "r"(a[1]), "r"(a[2]), "r"(a[3]), "r"(b[0]), "r"(b[1]));
}

// cp.async 16B, L1-bypass
__device__ __forceinline__ void cp16(unsigned dst, const unsigned* src) {
    asm volatile("cp.async.cg.shared.global [%0], [%1], 16;"
        :: "r"(dst), "l"(src));
}
#define CP_COMMIT() asm volatile("cp.async.commit_group;" ::: "memory")
#define CP_WAIT(n)  asm volatile("cp.async.wait_group %0;" :: "n"(n) : "memory")

// ===========================================================================
// Kernel 0: W pre-split (fp32 -> packed bf16 hi/lo), 192 x 1024 elements.
// ===========================================================================
__global__ __launch_bounds__(256) void wsplit_kernel(
    const float* __restrict__ Wq, const float* __restrict__ Wk,
    const float* __restrict__ Wv)
{
    int idx = blockIdx.x * 256 + threadIdx.x;   // 0..98303 (uint pairs)
    int row = idx >> 9;                         // 0..191
    int d2 = idx & 511;
    const float* W = (row < 64) ? Wq : (row < 128 ? Wk : Wv);
    int r = row & 63;
    float2 f = *(const float2*)&W[(size_t)r * NC + d2 * 2];
    unsigned hp, lp;
    split2(f.x, f.y, hp, lp);
    g_whi[idx] = hp;
    g_wlo[idx] = lp;
}

// ===========================================================================
// Kernel 1: fused QKV projection on mma.sync (bf16x3), software-pipelined.
// (identical to R15's passing version)
// ===========================================================================
#define QK_X0 0             // X buf: hi at +0, lo at +18432 (128 x 144 each)
#define QK_X1 36864
#define QK_W0 73728         // W buf: hi at +0, lo at +27648 (192 x 144 each)
#define QK_W1 129024
#define QK_TOTAL 184320

__device__ __forceinline__ void qk_stage_w(unsigned dstbase, int tid, int kc) {
#pragma unroll
    for (int i = 0; i < 6; i++) {
        int idx = tid + i * 256;     // 0..1535
        int rr = idx >> 3;           // row 0..191
        int c = idx & 7;
        cp16(dstbase + rr * 144 + c * 16, g_whi + rr * 512 + kc * 32 + c * 4);
        cp16(dstbase + 27648 + rr * 144 + c * 16, g_wlo + rr * 512 + kc * 32 + c * 4);
    }
}

__device__ __forceinline__ void qk_load_x(float2* xr, const float* x,
                                          int row0, int kc, int tid) {
#pragma unroll
    for (int i = 0; i < 16; i++) {
        int idx = tid + i * 256;
        int rr = idx >> 5;
        int d2 = idx & 31;
        xr[i] = *(const float2*)&x[(size_t)(row0 + rr) * NC + kc * 64 + d2 * 2];
    }
}

__device__ __forceinline__ void qk_store_x(char* sm, unsigned base,
                                           const float2* xr, int tid) {
#pragma unroll
    for (int i = 0; i < 16; i++) {
        int idx = tid + i * 256;
        int rr = idx >> 5;
        int d2 = idx & 31;
        unsigned hp, lp;
        split2(xr[i].x, xr[i].y, hp, lp);
        *(unsigned*)(sm + base + rr * 144 + d2 * 4) = hp;
        *(unsigned*)(sm + base + 18432 + rr * 144 + d2 * 4) = lp;
    }
}

__global__ __launch_bounds__(256, 1) void qkv_kernel(
    const float* __restrict__ x,
    const float* __restrict__ bq, const float* __restrict__ bk,
    const float* __restrict__ bv)
{
    extern __shared__ char sm[];
    unsigned smb = smem_to_u32(sm);

    int tid = threadIdx.x;
    int lane = tid & 31;
    int wid = tid >> 5;
    int mw = wid & 3;           // rows mw*32 .. +31
    int nh = wid >> 2;          // cols nh*96 .. +95
    int row0 = blockIdx.x * 128;

    float cO[2][12][4] = {};
    float2 xr[16];

    // ---- prologue: stage chunk 0 ----
    qk_load_x(xr, x, row0, 0, tid);
    qk_stage_w(smb + QK_W0, tid, 0);
    CP_COMMIT();
    qk_store_x(sm, QK_X0, xr, tid);
    CP_WAIT(0);
    __syncthreads();

    for (int kc = 0; kc < 16; kc++) {
        int cur = kc & 1;
        unsigned xb = smb + (cur ? QK_X1 : QK_X0);
        unsigned wb = smb + (cur ? QK_W1 : QK_W0);

        if (kc < 15) {
            qk_stage_w(smb + (cur ? QK_W0 : QK_W1), tid, kc + 1);
            CP_COMMIT();
            qk_load_x(xr, x, row0, kc + 1, tid);
        }

        // ---- MMA: warp tile 32 rows x 96 cols, bf16x3 ----
#pragma unroll
        for (int ks = 0; ks < 4; ks++) {
            unsigned ah[2][4], al[2][4];
#pragma unroll
            for (int mi = 0; mi < 2; mi++) {
                unsigned xoff = (unsigned)((mw * 32 + mi * 16 + (lane & 15)) * 144 +
                                           (ks * 16 + (lane >> 4) * 8) * 2);
                ldsm4(ah[mi], xb + xoff);
                ldsm4(al[mi], xb + 18432 + xoff);
            }
            unsigned bh[12][2], bl[12][2];
#pragma unroll
            for (int np = 0; np < 6; np++) {
                unsigned woff = (unsigned)((nh * 96 + np * 16 + (lane >> 4) * 8 +
                                            (lane & 7)) * 144 +
                                           (ks * 16 + ((lane >> 3) & 1) * 8) * 2);
                unsigned r[4];
                ldsm4(r, wb + woff);
                bh[2 * np][0] = r[0]; bh[2 * np][1] = r[1];
                bh[2 * np + 1][0] = r[2]; bh[2 * np + 1][1] = r[3];
                ldsm4(r, wb + 27648 + woff);
                bl[2 * np][0] = r[0]; bl[2 * np][1] = r[1];
                bl[2 * np + 1][0] = r[2]; bl[2 * np + 1][1] = r[3];
            }
#pragma unroll
            for (int mi = 0; mi < 2; mi++)
#pragma unroll
                for (int nj = 0; nj < 12; nj++) {
                    mma16816(cO[mi][nj], ah[mi], bh[nj]);
                    mma16816(cO[mi][nj], ah[mi], bl[nj]);
                    mma16816(cO[mi][nj], al[mi], bh[nj]);
                }
        }

        if (kc < 15) {
            qk_store_x(sm, cur ? QK_X0 : QK_X1, xr, tid);
            CP_WAIT(0);
        }
        __syncthreads();
    }

    // ---- epilogue: add bias; Q/K -> bf16 hi/lo split, V -> single fp16 ----
    const float QSCALE = 8.0f * 1.4426950408889634f;   // fold exp2 domain into Q
#pragma unroll
    for (int mi = 0; mi < 2; mi++)
#pragma unroll
        for (int nj = 0; nj < 12; nj++) {
            int gc = nh * 96 + nj * 8 + 2 * (lane & 3);   // global col, even
            int r0 = row0 + mw * 32 + mi * 16 + (lane >> 2);
            if (gc < 128) {
                unsigned *dhi, *dlo;
                const float* bias;
                int col;
                float scale;
                if (gc < 64) { dhi = g_qhi; dlo = g_qlo; bias = bq; col = gc; scale = QSCALE; }
                else         { dhi = g_khi; dlo = g_klo; bias = bk; col = gc - 64; scale = 1.0f; }
                float b0 = __ldg(&bias[col]);
                float b1 = __ldg(&bias[col + 1]);
                unsigned hp, lp;
                split2((cO[mi][nj][0] + b0) * scale, (cO[mi][nj][1] + b1) * scale, hp, lp);
                dhi[(size_t)r0 * 32 + col / 2] = hp;
                dlo[(size_t)r0 * 32 + col / 2] = lp;
                split2((cO[mi][nj][2] + b0) * scale, (cO[mi][nj][3] + b1) * scale, hp, lp);
                dhi[(size_t)(r0 + 8) * 32 + col / 2] = hp;
                dlo[(size_t)(r0 + 8) * 32 + col / 2] = lp;
            } else {
                int col = gc - 128;
                float b0 = __ldg(&bv[col]);
                float b1 = __ldg(&bv[col + 1]);
                g_vh[(size_t)r0 * 32 + col / 2] =
                    packh2(cO[mi][nj][0] + b0, cO[mi][nj][1] + b1);
                g_vh[(size_t)(r0 + 8) * 32 + col / 2] =
                    packh2(cO[mi][nj][2] + b0, cO[mi][nj][3] + b1);
            }
        }
}

// ===========================================================================
// Kernel 2: flash attention, 32-row warp tiles + kv-split partials.
// CTA = 128 q-rows (4 warps x 32 rows), kv range split in 2.
// S = QK^T bf16x3; PV single fp16. 2 CTAs/SM; cp.async double buffer.
// K/V fragments shared across 2 m-frags -> ldsm per MMA halved.
// ===========================================================================
#define AT_QHI 0                 // 128 x 144 B = 18432
#define AT_QLO 18432
#define AT_KV  36864             // 2 stages x 27648 (khi, klo, vh @ 9216 each)
#define AT_STG 27648
#define AT_TOTAL 92160
#define NKT (NT / BK / NSPLIT)   // kv tiles per split = 32

__device__ __forceinline__ void stage_kv(unsigned smb, int s, int tid, int kt,
    const unsigned* khi, const unsigned* klo, const unsigned* vh)
{
    unsigned base = smb + AT_KV + s * AT_STG;
    const unsigned* gs[3] = {khi, klo, vh};
#pragma unroll
    for (int a = 0; a < 3; a++)
#pragma unroll
        for (int i = 0; i < 4; i++) {
            int idx = tid + i * 128;      // 0..511
            int rr = idx >> 3;
            int c = idx & 7;
            cp16(base + a * 9216 + rr * 144 + c * 16,
                 gs[a] + (size_t)(kt * BK + rr) * 32 + c * 4);
        }
}

__global__ __launch_bounds__(128, 2) void attn_kernel()
{
    extern __shared__ char sm[];
    unsigned smb = smem_to_u32(sm);

    int tid = threadIdx.x;
    int lane = tid & 31;
    int w = tid >> 5;            // warp 0..3: q rows w*32 .. +31
    int b = blockIdx.y;
    int z = blockIdx.z;          // kv split index
    int q0 = blockIdx.x * BQ;
    int mrow = w * 32;
    int kt0 = z * NKT;

    const unsigned* qhi = g_qhi + (size_t)b * NT * 32;
    const unsigned* qlo = g_qlo + (size_t)b * NT * 32;
    const unsigned* khi = g_khi + (size_t)b * NT * 32;
    const unsigned* klo = g_klo + (size_t)b * NT * 32;
    const unsigned* vh  = g_vh  + (size_t)b * NT * 32;

    // ---- stage Q (128 rows, already split & scaled), then first K/V tile ----
    {
        const unsigned* qs[2] = {qhi, qlo};
#pragma unroll
        for (int a = 0; a < 2; a++)
#pragma unroll
            for (int i = 0; i < 8; i++) {
                int idx = tid + i * 128;      // 0..1023
                int rr = idx >> 3;
                int c = idx & 7;
                cp16(smb + a * 18432 + rr * 144 + c * 16,
                     qs[a] + (size_t)(q0 + rr) * 32 + c * 4);
            }
    }
    CP_COMMIT();                                   // G0 = Q
    stage_kv(smb, 0, tid, kt0, khi, klo, vh);
    CP_COMMIT();                                   // G1 = KV0
    CP_WAIT(1);                                    // Q done
    __syncthreads();

    // ---- hoist Q fragments into registers (once): 2 m-frags x 4 ks ----
    unsigned qfh[2][4][4], qfl[2][4][4];
#pragma unroll
    for (int mi = 0; mi < 2; mi++)
#pragma unroll
        for (int ks = 0; ks < 4; ks++) {
            unsigned qoff = (unsigned)((mrow + mi * 16 + (lane & 15)) * 144 +
                                       (ks * 16 + (lane >> 4) * 8) * 2);
            ldsm4(qfh[mi][ks], smb + AT_QHI + qoff);
            ldsm4(qfl[mi][ks], smb + AT_QLO + qoff);
        }

    float cO[2][8][4] = {};
    float m_[2][2] = {{-1e30f, -1e30f}, {-1e30f, -1e30f}};
    float l_[2][2] = {{0.0f, 0.0f}, {0.0f, 0.0f}};

    for (int ki = 0; ki < NKT; ki++) {
        int s = ki & 1;
        unsigned kb = smb + AT_KV + s * AT_STG;          // khi base
        if (ki + 1 < NKT) {
            stage_kv(smb, s ^ 1, tid, kt0 + ki + 1, khi, klo, vh);
            CP_COMMIT();
            CP_WAIT(1);
        } else {
            CP_WAIT(0);
        }
        __syncthreads();

        // ---- S = Q K^T, bf16x3: warp tile 32 rows x 64 cols ----
        float cS[2][8][4] = {};
#pragma unroll
        for (int ks = 0; ks < 4; ks++) {  // d k-chunks of 16
            unsigned bh[8][2], bl[8][2];
#pragma unroll
            for (int np = 0; np < 4; np++) {
                unsigned koff = (unsigned)((np * 16 + (lane >> 4) * 8 +
                                            (lane & 7)) * 144 +
                                           (ks * 16 + ((lane >> 3) & 1) * 8) * 2);
                unsigned r[4];
                ldsm4(r, kb + koff);
                bh[2 * np][0] = r[0]; bh[2 * np][1] = r[1];
                bh[2 * np + 1][0] = r[2]; bh[2 * np + 1][1] = r[3];
                ldsm4(r, kb + 9216 + koff);
                bl[2 * np][0] = r[0]; bl[2 * np][1] = r[1];
                bl[2 * np + 1][0] = r[2]; bl[2 * np + 1][1] = r[3];
            }
#pragma unroll
            for (int mi = 0; mi < 2; mi++)
#pragma unroll
                for (int nj = 0; nj < 8; nj++) {
                    mma16816(cS[mi][nj], qfh[mi][ks], bh[nj]);
                    mma16816(cS[mi][nj], qfh[mi][ks], bl[nj]);
                    mma16816(cS[mi][nj], qfl[mi][ks], bh[nj]);
                }
        }

        // ---- warp-local online softmax (exp2 domain), per m-frag ----
#pragma unroll
        for (int mi = 0; mi < 2; mi++) {
            float alpha[2];
#pragma unroll
            for (int j = 0; j < 2; j++) {
                float v = -1e30f;
#pragma unroll
                for (int nj = 0; nj < 8; nj++)
                    v = fmaxf(v, fmaxf(cS[mi][nj][2 * j], cS[mi][nj][2 * j + 1]));
                v = fmaxf(v, __shfl_xor_sync(0xffffffffu, v, 1));
                v = fmaxf(v, __shfl_xor_sync(0xffffffffu, v, 2));
                float mn = fmaxf(m_[mi][j], v);
                alpha[j] = ex2(m_[mi][j] - mn);
                m_[mi][j] = mn;
            }
#pragma unroll
            for (int nj = 0; nj < 8; nj++) {
                cO[mi][nj][0] *= alpha[0];
                cO[mi][nj][1] *= alpha[0];
                cO[mi][nj][2] *= alpha[1];
                cO[mi][nj][3] *= alpha[1];
            }
#pragma unroll
            for (int j = 0; j < 2; j++) {
                float s2 = 0.0f;
#pragma unroll
                for (int nj = 0; nj < 8; nj++) {
                    float e0 = ex2(cS[mi][nj][2 * j] - m_[mi][j]);
                    float e1 = ex2(cS[mi][nj][2 * j + 1] - m_[mi][j]);
                    cS[mi][nj][2 * j] = e0;
                    cS[mi][nj][2 * j + 1] = e1;
                    s2 += e0 + e1;
                }
                s2 += __shfl_xor_sync(0xffffffffu, s2, 1);
                s2 += __shfl_xor_sync(0xffffffffu, s2, 2);
                l_[mi][j] = l_[mi][j] * alpha[j] + s2;
            }
        }

        // ---- convert P (c-frag -> a-frag identity), single fp16 ----
        unsigned ph[2][4][4];             // [mi][ks2][reg]
#pragma unroll
        for (int mi = 0; mi < 2; mi++)
#pragma unroll
            for (int ks2 = 0; ks2 < 4; ks2++) {
                ph[mi][ks2][0] = packh2(cS[mi][2 * ks2][0],     cS[mi][2 * ks2][1]);
                ph[mi][ks2][1] = packh2(cS[mi][2 * ks2][2],     cS[mi][2 * ks2][3]);
                ph[mi][ks2][2] = packh2(cS[mi][2 * ks2 + 1][0], cS[mi][2 * ks2 + 1][1]);
                ph[mi][ks2][3] = packh2(cS[mi][2 * ks2 + 1][2], cS[mi][2 * ks2 + 1][3]);
            }

        // ---- O += P V (full k = 64), single fp16 MMA, V shared across mi ----
#pragma unroll
        for (int ks2 = 0; ks2 < 4; ks2++) {
            unsigned vhf[4][4];              // [npj][reg]
#pragma unroll
            for (int npj = 0; npj < 4; npj++) {
                unsigned voff = (unsigned)((ks2 * 16 + ((lane >> 3) & 1) * 8 +
                                            (lane & 7)) * 144 +
                                           (npj * 16 + (lane >> 4) * 8) * 2);
                ldsm4t(vhf[npj], kb + 18432 + voff);
            }
#pragma unroll
            for (int mi = 0; mi < 2; mi++)
#pragma unroll
                for (int nj = 0; nj < 8; nj++)
                    mma16816h(cO[mi][nj], ph[mi][ks2], &vhf[nj >> 1][(nj & 1) * 2]);
        }
        __syncthreads();   // stage-s readers done before ki+2 overwrites it
    }

    // ---- epilogue: write unnormalized partial O + (m, l) ----
#pragma unroll
    for (int mi = 0; mi < 2; mi++) {
        int r0 = q0 + mrow + mi * 16 + (lane >> 2);
        size_t pbase = ((size_t)(z * NB + b) * NT + r0) * ND;
#pragma unroll
        for (int nj = 0; nj < 8; nj++) {
            int c0 = nj * 8 + 2 * (lane & 3);
            *(float2*)&g_po[pbase + c0] = make_float2(cO[mi][nj][0], cO[mi][nj][1]);
            *(float2*)&g_po[pbase + (size_t)8 * ND + c0] =
                make_float2(cO[mi][nj][2], cO[mi][nj][3]);
        }
        if ((lane & 3) == 0) {
            size_t mb = (size_t)(z * NB + b) * NT + r0;
            g_pm[mb] = m_[mi][0];
            g_pl[mb] = l_[mi][0];
            g_pm[mb + 8] = m_[mi][1];
            g_pl[mb + 8] = l_[mi][1];
        }
    }
}

// ===========================================================================
// Kernel 3: combine the NSPLIT kv partials, normalize, store output.
// ===========================================================================
__global__ __launch_bounds__(256) void combine_kernel(float* __restrict__ out)
{
    int idx = blockIdx.x * 256 + threadIdx.x;   // 0 .. NB*NT*16-1
    int c4 = (idx & 15) * 4;                    // col 0..60
    int row = (idx >> 4) & (NT - 1);
    int b = idx >> 16;                          // NT*16 = 65536 per batch

    size_t m0i = (size_t)b * NT + row;
    size_t m1i = (size_t)(NB + b) * NT + row;
    float m0 = g_pm[m0i], m1 = g_pm[m1i];
    float l0 = g_pl[m0i], l1 = g_pl[m1i];
    float M = fmaxf(m0, m1);
    float a0 = ex2(m0 - M), a1 = ex2(m1 - M);
    float inv = 1.0f / (l0 * a0 + l1 * a1);

    float4 O0 = *(const float4*)&g_po[m0i * ND + c4];
    float4 O1 = *(const float4*)&g_po[m1i * ND + c4];
    float4 r;
    r.x = (O0.x * a0 + O1.x * a1) * inv;
    r.y = (O0.y * a0 + O1.y * a1) * inv;
    r.z = (O0.z * a0 + O1.z * a1) * inv;
    r.w = (O0.w * a0 + O1.w * a1) * inv;
    *(float4*)&out[((size_t)b * NT + row) * ND + c4] = r;
}

// ===========================================================================
extern "C" void kernel_launch(void* const* d_in, const int* in_sizes, int n_in,
                              void* d_out, int out_size)
{
    (void)in_sizes; (void)n_in; (void)out_size;
    const float* x  = (const float*)d_in[0];
    const float* Wq = (const float*)d_in[1];
    const float* bq = (const float*)d_in[2];
    const float* Wk = (const float*)d_in[3];
    const float* bk = (const float*)d_in[4];
    const float* Wv = (const float*)d_in[5];
    const float* bv = (const float*)d_in[6];
    float* out = (float*)d_out;

    // 0: pre-split W into bf16 hi/lo (192*512 uint pairs)
    wsplit_kernel<<<384, 256>>>(Wq, Wk, Wv);

    // 1: fused QKV projection (tensor cores, software-pipelined)
    cudaFuncSetAttribute(qkv_kernel,
                         cudaFuncAttributeMaxDynamicSharedMemorySize,
                         QK_TOTAL);
    qkv_kernel<<<(NB * NT) / 128, 256, QK_TOTAL>>>(x, bq, bk, bv);

    // 2: flash attention kv-split partials (32-row warps, 2 CTAs/SM, 256 CTAs)
    cudaFuncSetAttribute(attn_kernel,
                         cudaFuncAttributeMaxDynamicSharedMemorySize,
                         AT_TOTAL);
    attn_kernel<<<dim3(NT / BQ, NB, NSPLIT), 128, AT_TOTAL>>>();

    // 3: combine partials, normalize
    combine_kernel<<<NB * NT * 16 / 256, 256>>>(out);
}